// round 7
// baseline (speedup 1.0000x reference)
#include <cuda_runtime.h>
#include <cuda_bf16.h>
#include <cstdint>

#define ROWS_REAL 9800          // 2 * 70 * 70 padded-grid rows
#define ROWS_PAD  9856          // 77 * 128
#define NOUT      768           // q | kf | vf packed
#define K3        768           // split-K: [hi | hi | lo] x [hi | lo | hi]

__device__ __nv_bfloat16 g_A3[ROWS_PAD * K3];   // [row][k3]
__device__ __nv_bfloat16 g_B3[NOUT * K3];       // [n][k3]  (B^T, K-major)
__device__ float g_C[ROWS_PAD * NOUT];          // [q | kf | vf]
__device__ float g_bwin[49 * 256];              // transposed bias window [j][c]

// ---------------- helpers ----------------
__device__ __forceinline__ int reflect64(int i) {
    if (i < 0) i = -i - 1;
    if (i > 63) i = 127 - i;
    return i;
}
__device__ __forceinline__ float ex2f(float x) {
    float r;
    asm("ex2.approx.ftz.f32 %0, %1;" : "=f"(r) : "f"(x));
    return r;
}
__device__ __forceinline__ uint32_t smem_u32(const void* p) {
    uint32_t a;
    asm("{ .reg .u64 t; cvta.to.shared.u64 t, %1; cvt.u32.u64 %0, t; }" : "=r"(a) : "l"(p));
    return a;
}
__device__ __forceinline__ void cp16(uint32_t dst, const void* src) {
    asm volatile("cp.async.cg.shared.global [%0], [%1], 16;" :: "r"(dst), "l"(src));
}
__device__ __forceinline__ void ldsm4(uint32_t* d, uint32_t addr) {
    asm volatile("ldmatrix.sync.aligned.m8n8.x4.shared.b16 {%0,%1,%2,%3}, [%4];"
                 : "=r"(d[0]), "=r"(d[1]), "=r"(d[2]), "=r"(d[3]) : "r"(addr));
}
__device__ __forceinline__ void mma16816(float* c, const uint32_t* a, uint32_t b0, uint32_t b1) {
    asm volatile(
        "mma.sync.aligned.m16n8k16.row.col.f32.bf16.bf16.f32 "
        "{%0,%1,%2,%3}, {%4,%5,%6,%7}, {%8,%9}, {%0,%1,%2,%3};"
        : "+f"(c[0]), "+f"(c[1]), "+f"(c[2]), "+f"(c[3])
        : "r"(a[0]), "r"(a[1]), "r"(a[2]), "r"(a[3]), "r"(b0), "r"(b1));
}

// ---------------- prep: A3 = [hi | hi | lo] of symmetric-padded x, bf16 ----------------
__global__ void prep_a3_kernel(const float* __restrict__ x) {
    int p = blockIdx.x * blockDim.x + threadIdx.x;    // pair index
    if (p >= ROWS_PAD * 384) return;
    int r   = p / 384;
    int kk2 = p - r * 384;
    int k3  = kk2 * 2;
    int seg = k3 >> 8;
    int k   = k3 & 255;
    __nv_bfloat162 o;
    if (r < ROWS_REAL) {
        int b   = r / 4900;
        int rem = r - b * 4900;
        int hp  = rem / 70;
        int wp  = rem - hp * 70;
        int hs  = reflect64(hp - 3);
        int ws  = reflect64(wp - 3);
        const float* src = x + ((((b << 6) + hs) << 6) + ws) * 256;
        float v0 = src[k], v1 = src[k + 1];
        __nv_bfloat16 h0 = __float2bfloat16(v0);
        __nv_bfloat16 h1 = __float2bfloat16(v1);
        if (seg < 2) {
            o.x = h0; o.y = h1;
        } else {
            o.x = __float2bfloat16(v0 - __bfloat162float(h0));
            o.y = __float2bfloat16(v1 - __bfloat162float(h1));
        }
    } else {
        o.x = __float2bfloat16(0.f); o.y = __float2bfloat16(0.f);
    }
    *(__nv_bfloat162*)(g_A3 + r * K3 + k3) = o;
}

// ---------------- prep: B3[n][k3] = [hi | lo | hi] of wcat, bf16 ----------------
__global__ void prep_b3_kernel(const float* __restrict__ wq,
                               const float* __restrict__ wk,
                               const float* __restrict__ wv) {
    int p = blockIdx.x * blockDim.x + threadIdx.x;
    if (p >= NOUT * 384) return;
    int n   = p / 384;
    int kk2 = p - n * 384;
    int k3  = kk2 * 2;
    int seg = k3 >> 8;
    int k   = k3 & 255;
    int sel = n >> 8;
    int cc  = n & 255;
    const float* w = (sel == 0) ? wq : (sel == 1 ? wk : wv);
    float v0 = w[k * 256 + cc];
    float v1 = w[(k + 1) * 256 + cc];
    __nv_bfloat16 h0 = __float2bfloat16(v0);
    __nv_bfloat16 h1 = __float2bfloat16(v1);
    __nv_bfloat162 o;
    if (seg == 1) {
        o.x = __float2bfloat16(v0 - __bfloat162float(h0));
        o.y = __float2bfloat16(v1 - __bfloat162float(h1));
    } else {
        o.x = h0; o.y = h1;
    }
    *(__nv_bfloat162*)(g_B3 + n * K3 + k3) = o;
}

// ---------------- prep: transposed bias window table Bwin[j][c] ----------------
__global__ void prep_bwin_kernel(const float* __restrict__ rh,
                                 const float* __restrict__ rw) {
    int idx = blockIdx.x * blockDim.x + threadIdx.x;
    if (idx >= 49 * 256) return;
    int j = idx >> 8;
    int c = idx & 255;
    int u = c * 49 + j;
    int ch = u & 255;
    int tap = u >> 8;
    int kh = (tap * 37) >> 8;
    int kw = tap - kh * 7;
    g_bwin[idx] = (ch < 128) ? rh[kh * 128 + ch] : rw[kw * 128 + (ch - 128)];
}

// ---------------- mma.sync GEMM: C[9856,768] = A3 . B3^T ----------------
// BM=128 BN=128 BK=32, 8 warps (2x4), warp tile 64x32, 4-stage cp.async ring,
// ONE __syncthreads per k-iter. 80B smem pitch -> conflict-free ldmatrix.
#define PITCH 80
#define ABYTES (128 * PITCH)      // 10240
#define BUFBYTES (2 * ABYTES)     // 20480 per stage
#define STAGES 4
#define GSMEM (STAGES * BUFBYTES) // 81920

__global__ __launch_bounds__(256, 2) void mma_gemm_kernel() {
    extern __shared__ __align__(16) char smem[];
    uint32_t sb = smem_u32(smem);

    int tid = threadIdx.x;
    int lane = tid & 31, wid = tid >> 5;
    int wm = wid >> 2, wn = wid & 3;                    // 2 x 4 warp grid
    int row0 = blockIdx.y * 128, col0 = blockIdx.x * 128;

    const __nv_bfloat16* Ag = g_A3 + (size_t)row0 * K3;
    const __nv_bfloat16* Bg = g_B3 + (size_t)col0 * K3;

    int sr  = tid >> 1;             // staged row 0..127
    int sg  = (tid & 1) * 2;        // 16B chunk pair
    uint32_t stA = sb + sr * PITCH + sg * 16;
    uint32_t stB = stA + ABYTES;

    int arow = (lane & 7) + (((lane >> 3) & 1) << 3);
    int akc  = (lane >> 4) * 16;
    int brow = (lane & 7) + ((lane >> 4) << 3);
    int bkc  = ((lane >> 3) & 1) * 16;

    float acc[4][4][4];
#pragma unroll
    for (int i = 0; i < 4; i++)
#pragma unroll
        for (int j = 0; j < 4; j++)
#pragma unroll
            for (int v = 0; v < 4; v++) acc[i][j][v] = 0.f;

    // prologue: stage k-chunks 0..2
#pragma unroll
    for (int s = 0; s < 3; s++) {
        uint32_t off = s * BUFBYTES;
        const __nv_bfloat16* a = Ag + sr * K3 + s * 32 + sg * 8;
        const __nv_bfloat16* b = Bg + sr * K3 + s * 32 + sg * 8;
        cp16(stA + off, a); cp16(stA + off + 16, a + 8);
        cp16(stB + off, b); cp16(stB + off + 16, b + 8);
        asm volatile("cp.async.commit_group;");
    }

    for (int kt = 0; kt < 24; kt++) {
        if (kt < 22)      asm volatile("cp.async.wait_group 2;");
        else if (kt == 22) asm volatile("cp.async.wait_group 1;");
        else              asm volatile("cp.async.wait_group 0;");
        __syncthreads();

        if (kt < 21) {
            uint32_t off = (uint32_t)((kt + 3) & 3) * BUFBYTES;
            const __nv_bfloat16* a = Ag + sr * K3 + (kt + 3) * 32 + sg * 8;
            const __nv_bfloat16* b = Bg + sr * K3 + (kt + 3) * 32 + sg * 8;
            cp16(stA + off, a); cp16(stA + off + 16, a + 8);
            cp16(stB + off, b); cp16(stB + off + 16, b + 8);
            asm volatile("cp.async.commit_group;");
        }

        uint32_t aBase = sb + (uint32_t)(kt & 3) * BUFBYTES;
        uint32_t bBase = aBase + ABYTES;
#pragma unroll
        for (int ks = 0; ks < 2; ks++) {
            uint32_t af[4][4];
#pragma unroll
            for (int mt = 0; mt < 4; mt++)
                ldsm4(af[mt], aBase + (uint32_t)((wm * 64 + mt * 16 + arow) * PITCH + ks * 32 + akc));
            uint32_t bf[2][4];
#pragma unroll
            for (int nh = 0; nh < 2; nh++)
                ldsm4(bf[nh], bBase + (uint32_t)((wn * 32 + nh * 16 + brow) * PITCH + ks * 32 + bkc));
#pragma unroll
            for (int mt = 0; mt < 4; mt++)
#pragma unroll
                for (int nt = 0; nt < 4; nt++)
                    mma16816(acc[mt][nt], af[mt],
                             bf[nt >> 1][(nt & 1) * 2], bf[nt >> 1][(nt & 1) * 2 + 1]);
        }
    }

    // epilogue: m16n8 fragment -> g_C
    int qr = lane >> 2;
    int qc = (lane & 3) * 2;
#pragma unroll
    for (int mt = 0; mt < 4; mt++) {
#pragma unroll
        for (int nt = 0; nt < 4; nt++) {
            int rr = row0 + wm * 64 + mt * 16 + qr;
            int cc = col0 + wn * 32 + nt * 8 + qc;
            *(float2*)(g_C + (size_t)rr * 768 + cc)       = make_float2(acc[mt][nt][0], acc[mt][nt][1]);
            *(float2*)(g_C + (size_t)(rr + 8) * 768 + cc) = make_float2(acc[mt][nt][2], acc[mt][nt][3]);
        }
    }
}

// ---------------- attention: 2x2 tile, interleaved (K,V) pairs, LDS.64 taps ----------------
__global__ __launch_bounds__(512, 1) void attn_kernel(float* __restrict__ out) {
    extern __shared__ float sm[];          // 64 rows x 512 floats (K,V interleaved) = 128 KB
    float2* sm2 = (float2*)sm;
    float4* sm4 = (float4*)sm;

    int t = threadIdx.x;
    int bid = blockIdx.x;
    int w2 = bid & 31, h2 = (bid >> 5) & 31, b = bid >> 10;
    int h0 = h2 * 2, w0 = w2 * 2;

    // stage interleaved KV: idx over 8192 (64 rows x 128 out-float4s), 16 iters.
    // out float4 g holds channels (2g, 2g+1) as (k0,v0,k1,v1).
#pragma unroll
    for (int i = 0; i < 16; i++) {
        int idx = i * 512 + t;
        int r = idx >> 7;              // tile row: (h offset)*8 + (w offset)
        int g = idx & 127;
        int rr8 = r >> 3, rc = r & 7;
        const float* base = g_C + (size_t)((b * 70 + h0 + rr8) * 70 + (w0 + rc)) * 768;
        float2 kg = *(const float2*)(base + 256 + 2 * g);
        float2 vg = *(const float2*)(base + 512 + 2 * g);
        sm4[r * 128 + g] = make_float4(kg.x, vg.x, kg.y, vg.y);
    }
    __syncthreads();

    int slot = t >> 8;
    int c = t & 255;
    int u0 = c * 49;
    int tap0 = u0 >> 8;
    int ch0 = u0 & 255;
    int kh0 = (tap0 * 37) >> 8;
    int kw0 = tap0 - kh0 * 7;
    int n1 = 256 - ch0; if (n1 > 49) n1 = 49;
    int kh1 = kh0, kw1 = kw0 + 1;
    if (kw1 == 7) { kw1 = 0; kh1++; }

    float breg[49];
#pragma unroll
    for (int j = 0; j < 49; j++)
        breg[j] = __ldg(&g_bwin[j * 256 + c]);

#pragma unroll
    for (int p = 0; p < 2; p++) {
        int posid = slot * 2 + p;
        int dh = posid >> 1, dw = posid & 1;
        float q = g_C[((b * 70 + h0 + dh + 3) * 70 + (w0 + dw + 3)) * 768 + c];
        float ql2 = q * 1.4426950408889634f;

        int baseA = (((dh + kh0) << 3) + dw + kw0) * 256 + ch0;   // pair units
        int baseB = (((dh + kh1) << 3) + dw + kw1) * 256 - n1;

        float s0 = 0.f, s1 = 0.f, a0 = 0.f, a1 = 0.f;
#pragma unroll
        for (int j = 0; j < 49; j++) {
            int a = (j < n1) ? baseA : baseB;
            float2 kv = sm2[a + j];
            float e = ex2f(ql2 * kv.x);
            if (j & 1) { s1 += e; a1 += e * (kv.y + breg[j]); }
            else       { s0 += e; a0 += e * (kv.y + breg[j]); }
        }
        out[((b * 64 + h0 + dh) * 64 + (w0 + dw)) * 256 + c] = (a0 + a1) / (s0 + s1);
    }
}

// ---------------- launch ----------------
extern "C" void kernel_launch(void* const* d_in, const int* in_sizes, int n_in,
                              void* d_out, int out_size) {
    const float* x  = (const float*)d_in[0];
    const float* wq = (const float*)d_in[1];
    const float* wk = (const float*)d_in[2];
    const float* wv = (const float*)d_in[3];
    const float* rh = (const float*)d_in[4];
    const float* rw = (const float*)d_in[5];
    float* out = (float*)d_out;

    prep_a3_kernel<<<(ROWS_PAD * 384 + 255) / 256, 256>>>(x);
    prep_b3_kernel<<<(NOUT * 384 + 255) / 256, 256>>>(wq, wk, wv);
    prep_bwin_kernel<<<49, 256>>>(rh, rw);

    cudaFuncSetAttribute(mma_gemm_kernel,
                         cudaFuncAttributeMaxDynamicSharedMemorySize, GSMEM);
    dim3 ggrid(6, 77);   // N-tiles x M-tiles
    mma_gemm_kernel<<<ggrid, 256, GSMEM>>>();

    cudaFuncSetAttribute(attn_kernel,
                         cudaFuncAttributeMaxDynamicSharedMemorySize, 131072);
    attn_kernel<<<2048, 512, 131072>>>(out);
}

// round 8
// speedup vs baseline: 1.2685x; 1.2685x over previous
#include <cuda_runtime.h>
#include <cuda_bf16.h>
#include <cstdint>

#define ROWS_REAL 9800          // 2 * 70 * 70 padded-grid rows
#define ROWS_PAD  9856          // 77 * 128 = 616 * 16
#define NOUT      768           // q | kf | vf packed
#define K3        768           // split-K: [hi | hi | lo] x [hi | lo | hi]
#define NR16      616           // ROWS_PAD / 16
#define NK16      48            // K3 / 16
#define NN8       96            // NOUT / 8

// Fragment-linear operand storage:
//   A3f: [R16 frag][K16 frag][lane 0..31][8 bf16]   (a0|a1|a2|a3 pairs)
//   B3f: [N8 frag][K16 frag][lane 0..31][4 bf16]    (b0|b1 pairs)
__device__ __nv_bfloat16 g_A3f[NR16 * NK16 * 32 * 8];
__device__ __nv_bfloat16 g_B3f[NN8 * NK16 * 32 * 4];
__device__ float g_C[ROWS_PAD * NOUT];          // [q | kf | vf]
__device__ float g_bwin[49 * 256];              // transposed bias window [j][c]

// ---------------- helpers ----------------
__device__ __forceinline__ int reflect64(int i) {
    if (i < 0) i = -i - 1;
    if (i > 63) i = 127 - i;
    return i;
}
__device__ __forceinline__ float ex2f(float x) {
    float r;
    asm("ex2.approx.ftz.f32 %0, %1;" : "=f"(r) : "f"(x));
    return r;
}
__device__ __forceinline__ void mma16816(float* c, const uint32_t* a, uint32_t b0, uint32_t b1) {
    asm volatile(
        "mma.sync.aligned.m16n8k16.row.col.f32.bf16.bf16.f32 "
        "{%0,%1,%2,%3}, {%4,%5,%6,%7}, {%8,%9}, {%0,%1,%2,%3};"
        : "+f"(c[0]), "+f"(c[1]), "+f"(c[2]), "+f"(c[3])
        : "r"(a[0]), "r"(a[1]), "r"(a[2]), "r"(a[3]), "r"(b0), "r"(b1));
}
__device__ __forceinline__ __nv_bfloat16 bf_hi(float v) { return __float2bfloat16(v); }
__device__ __forceinline__ __nv_bfloat16 bf_lo(float v) {
    __nv_bfloat16 h = __float2bfloat16(v);
    return __float2bfloat16(v - __bfloat162float(h));
}

// ---------------- prep: A fragments (symmetric-padded x, [hi|hi|lo] split) ----------------
// One thread per (frag, lane): writes 16B = regs a0..a3 (pairs).
__global__ void prep_a3f_kernel(const float* __restrict__ x) {
    int tid = blockIdx.x * blockDim.x + threadIdx.x;
    if (tid >= NR16 * NK16 * 32) return;
    int lane = tid & 31;
    int f = tid >> 5;
    int K16 = f % NK16;
    int R16 = f / NK16;
    int seg = (K16 * 16) >> 8;               // constant within frag (16 | 256)
    int kc  = ((K16 * 16) & 255) + (lane & 3) * 2;
    bool lo = (seg == 2);                    // A3 = [hi | hi | lo]

    int re = R16 * 16 + (lane >> 2);         // rows for a0/a2
    int ro = re + 8;                         // rows for a1/a3

    const float* pe = nullptr;
    const float* po = nullptr;
    if (re < ROWS_REAL) {
        int b = re / 4900, rem = re - b * 4900;
        int hp = rem / 70, wp = rem - hp * 70;
        pe = x + ((((b << 6) + reflect64(hp - 3)) << 6) + reflect64(wp - 3)) * 256;
    }
    if (ro < ROWS_REAL) {
        int b = ro / 4900, rem = ro - b * 4900;
        int hp = rem / 70, wp = rem - hp * 70;
        po = x + ((((b << 6) + reflect64(hp - 3)) << 6) + reflect64(wp - 3)) * 256;
    }

    __nv_bfloat16 o[8];
#pragma unroll
    for (int h = 0; h < 2; h++) {
        float ve0 = pe ? pe[kc + h]     : 0.f;
        float vo0 = po ? po[kc + h]     : 0.f;
        float ve8 = pe ? pe[kc + 8 + h] : 0.f;
        float vo8 = po ? po[kc + 8 + h] : 0.f;
        o[0 + h] = lo ? bf_lo(ve0) : bf_hi(ve0);   // a0
        o[2 + h] = lo ? bf_lo(vo0) : bf_hi(vo0);   // a1
        o[4 + h] = lo ? bf_lo(ve8) : bf_hi(ve8);   // a2
        o[6 + h] = lo ? bf_lo(vo8) : bf_hi(vo8);   // a3
    }
    *(uint4*)(g_A3f + (size_t)tid * 8) = *(uint4*)o;
}

// ---------------- prep: B fragments (wcat^T, [hi|lo|hi] split) ----------------
__global__ void prep_b3f_kernel(const float* __restrict__ wq,
                                const float* __restrict__ wk,
                                const float* __restrict__ wv) {
    int tid = blockIdx.x * blockDim.x + threadIdx.x;
    if (tid >= NN8 * NK16 * 32) return;
    int lane = tid & 31;
    int f = tid >> 5;
    int K16 = f % NK16;
    int N8  = f / NK16;
    int seg = (K16 * 16) >> 8;
    int kc  = ((K16 * 16) & 255) + (lane & 3) * 2;
    bool lo = (seg == 1);                    // B3 = [hi | lo | hi]

    int n = N8 * 8 + (lane >> 2);
    int sel = n >> 8, cc = n & 255;
    const float* w = (sel == 0) ? wq : (sel == 1 ? wk : wv);

    __nv_bfloat16 o[4];
#pragma unroll
    for (int h = 0; h < 2; h++) {
        float v0 = w[(kc + h) * 256 + cc];        // b0: k = kc+h
        float v8 = w[(kc + 8 + h) * 256 + cc];    // b1: k+8
        o[0 + h] = lo ? bf_lo(v0) : bf_hi(v0);
        o[2 + h] = lo ? bf_lo(v8) : bf_hi(v8);
    }
    *(uint2*)(g_B3f + (size_t)tid * 4) = *(uint2*)o;
}

// ---------------- prep: transposed bias window table Bwin[j][c] ----------------
__global__ void prep_bwin_kernel(const float* __restrict__ rh,
                                 const float* __restrict__ rw) {
    int idx = blockIdx.x * blockDim.x + threadIdx.x;
    if (idx >= 49 * 256) return;
    int j = idx >> 8;
    int c = idx & 255;
    int u = c * 49 + j;
    int ch = u & 255;
    int tap = u >> 8;
    int kh = (tap * 37) >> 8;
    int kw = tap - kh * 7;
    g_bwin[idx] = (ch < 128) ? rh[kh * 128 + ch] : rw[kw * 128 + (ch - 128)];
}

// ---------------- smem-free mma.sync GEMM: C[9856,768] = A3 . B3^T ----------------
// BM=128 BN=128, 8 warps (2x4), warp tile 64x32. Fragments loaded straight from
// GMEM (L1/L2-cached, frag-linear): 4 LDG.128 + 4 LDG.64 + 16 MMA per K16 step.
__global__ __launch_bounds__(256, 2) void mma_gemm_kernel() {
    int tid = threadIdx.x;
    int lane = tid & 31, wid = tid >> 5;
    int wm = wid >> 2, wn = wid & 3;
    int fragR0 = blockIdx.y * 8  + wm * 4;    // R16 frag base
    int fragN0 = blockIdx.x * 16 + wn * 4;    // N8 frag base

    const uint4* Af = (const uint4*)g_A3f;    // index: (R16*NK16 + kt)*32 + lane
    const uint2* Bf = (const uint2*)g_B3f;    // index: (N8*NK16 + kt)*32 + lane

    const uint4* pA[4];
    const uint2* pB[4];
#pragma unroll
    for (int mt = 0; mt < 4; mt++) pA[mt] = Af + ((size_t)(fragR0 + mt) * NK16) * 32 + lane;
#pragma unroll
    for (int nt = 0; nt < 4; nt++) pB[nt] = Bf + ((size_t)(fragN0 + nt) * NK16) * 32 + lane;

    float acc[4][4][4];
#pragma unroll
    for (int i = 0; i < 4; i++)
#pragma unroll
        for (int j = 0; j < 4; j++)
#pragma unroll
            for (int v = 0; v < 4; v++) acc[i][j][v] = 0.f;

    uint4 a[4]; uint2 b[4];
    uint4 an[4]; uint2 bn[4];
#pragma unroll
    for (int mt = 0; mt < 4; mt++) a[mt] = pA[mt][0];
#pragma unroll
    for (int nt = 0; nt < 4; nt++) b[nt] = pB[nt][0];

#pragma unroll 4
    for (int kt = 0; kt < NK16; kt += 2) {
        // prefetch kt+1
#pragma unroll
        for (int mt = 0; mt < 4; mt++) an[mt] = pA[mt][(kt + 1) * 32];
#pragma unroll
        for (int nt = 0; nt < 4; nt++) bn[nt] = pB[nt][(kt + 1) * 32];
        // compute kt
#pragma unroll
        for (int mt = 0; mt < 4; mt++)
#pragma unroll
            for (int nt = 0; nt < 4; nt++)
                mma16816(acc[mt][nt], (const uint32_t*)&a[mt], b[nt].x, b[nt].y);
        // prefetch kt+2
        if (kt + 2 < NK16) {
#pragma unroll
            for (int mt = 0; mt < 4; mt++) a[mt] = pA[mt][(kt + 2) * 32];
#pragma unroll
            for (int nt = 0; nt < 4; nt++) b[nt] = pB[nt][(kt + 2) * 32];
        }
        // compute kt+1
#pragma unroll
        for (int mt = 0; mt < 4; mt++)
#pragma unroll
            for (int nt = 0; nt < 4; nt++)
                mma16816(acc[mt][nt], (const uint32_t*)&an[mt], bn[nt].x, bn[nt].y);
    }

    // epilogue: m16n8 fragments -> g_C
    int row0 = blockIdx.y * 128, col0 = blockIdx.x * 128;
    int qr = lane >> 2;
    int qc = (lane & 3) * 2;
#pragma unroll
    for (int mt = 0; mt < 4; mt++) {
#pragma unroll
        for (int nt = 0; nt < 4; nt++) {
            int rr = row0 + wm * 64 + mt * 16 + qr;
            int cc = col0 + wn * 32 + nt * 8 + qc;
            *(float2*)(g_C + (size_t)rr * 768 + cc)       = make_float2(acc[mt][nt][0], acc[mt][nt][1]);
            *(float2*)(g_C + (size_t)(rr + 8) * 768 + cc) = make_float2(acc[mt][nt][2], acc[mt][nt][3]);
        }
    }
}

// ---------------- attention: 2x2 spatial tile, branchless 2-base windows (R6 form) ----------------
__global__ __launch_bounds__(512, 1) void attn_kernel(float* __restrict__ out) {
    extern __shared__ float sm[];          // 64 rows x [K 256f | V 256f] = 32768 floats

    int t = threadIdx.x;
    int bid = blockIdx.x;
    int w2 = bid & 31, h2 = (bid >> 5) & 31, b = bid >> 10;
    int h0 = h2 * 2, w0 = w2 * 2;

    const float4* C4 = (const float4*)g_C;
    float4* sm4 = (float4*)sm;

#pragma unroll
    for (int i = 0; i < 16; i++) {
        int idx = i * 512 + t;
        int which = idx >> 12;             // 0=K, 1=V
        int rr = (idx >> 6) & 63;
        int ch4 = idx & 63;
        int rr8 = rr >> 3, rc = rr & 7;
        int grow = (b * 70 + h0 + rr8) * 70 + (w0 + rc);
        sm4[rr * 128 + (which << 6) + ch4] = C4[grow * 192 + 64 + (which << 6) + ch4];
    }
    __syncthreads();

    int slot = t >> 8;
    int c = t & 255;
    int u0 = c * 49;
    int tap0 = u0 >> 8;
    int ch0 = u0 & 255;
    int kh0 = (tap0 * 37) >> 8;
    int kw0 = tap0 - kh0 * 7;
    int n1 = 256 - ch0; if (n1 > 49) n1 = 49;
    int kh1 = kh0, kw1 = kw0 + 1;
    if (kw1 == 7) { kw1 = 0; kh1++; }

    float breg[49];
#pragma unroll
    for (int j = 0; j < 49; j++)
        breg[j] = __ldg(&g_bwin[j * 256 + c]);

#pragma unroll
    for (int p = 0; p < 2; p++) {
        int posid = slot * 2 + p;
        int dh = posid >> 1, dw = posid & 1;
        float q = g_C[((b * 70 + h0 + dh + 3) * 70 + (w0 + dw + 3)) * 768 + c];
        float ql2 = q * 1.4426950408889634f;

        int baseA = (((dh + kh0) << 3) + dw + kw0) * 512 + ch0;
        int baseB = (((dh + kh1) << 3) + dw + kw1) * 512 - n1;

        float s0 = 0.f, s1 = 0.f, a0 = 0.f, a1 = 0.f;
#pragma unroll
        for (int j = 0; j < 49; j++) {
            int a = (j < n1) ? baseA : baseB;
            float kv = sm[a + j];
            float vv = sm[a + j + 256];
            float e = ex2f(ql2 * kv);
            if (j & 1) { s1 += e; a1 += e * (vv + breg[j]); }
            else       { s0 += e; a0 += e * (vv + breg[j]); }
        }
        out[((b * 64 + h0 + dh) * 64 + (w0 + dw)) * 256 + c] = (a0 + a1) / (s0 + s1);
    }
}

// ---------------- launch ----------------
extern "C" void kernel_launch(void* const* d_in, const int* in_sizes, int n_in,
                              void* d_out, int out_size) {
    const float* x  = (const float*)d_in[0];
    const float* wq = (const float*)d_in[1];
    const float* wk = (const float*)d_in[2];
    const float* wv = (const float*)d_in[3];
    const float* rh = (const float*)d_in[4];
    const float* rw = (const float*)d_in[5];
    float* out = (float*)d_out;

    prep_a3f_kernel<<<(NR16 * NK16 * 32 + 255) / 256, 256>>>(x);
    prep_b3f_kernel<<<(NN8 * NK16 * 32 + 255) / 256, 256>>>(wq, wk, wv);
    prep_bwin_kernel<<<49, 256>>>(rh, rw);

    dim3 ggrid(6, 77);   // N-tiles x M-tiles
    mma_gemm_kernel<<<ggrid, 256>>>();

    cudaFuncSetAttribute(attn_kernel,
                         cudaFuncAttributeMaxDynamicSharedMemorySize, 131072);
    attn_kernel<<<2048, 512, 131072>>>(out);
}

// round 9
// speedup vs baseline: 1.3105x; 1.0330x over previous
#include <cuda_runtime.h>
#include <cuda_bf16.h>
#include <cstdint>

#define ROWS_REAL 9800          // 2 * 70 * 70 padded-grid rows
#define ROWS_PAD  9856          // 616 * 16
#define NOUT      768           // q | kf | vf packed
#define K3        768           // split-K: [hi | hi | lo] x [hi | lo | hi]
#define NR16      616           // ROWS_PAD / 16
#define NK16      48            // K3 / 16
#define NN8       96            // NOUT / 8

// Fragment-linear operand storage:
//   A3f: [R16 frag][K16 frag][lane 0..31][8 bf16]   (a0|a1|a2|a3 pairs)
//   B3f: [N8 frag][K16 frag][lane 0..31][4 bf16]    (b0|b1 pairs)
__device__ __nv_bfloat16 g_A3f[NR16 * NK16 * 32 * 8];
__device__ __nv_bfloat16 g_B3f[NN8 * NK16 * 32 * 4];
__device__ float g_C[ROWS_PAD * NOUT];          // [q | kf | vf]
__device__ float g_bwin[49 * 256];              // transposed bias window [j][c]

// ---------------- helpers ----------------
__device__ __forceinline__ int reflect64(int i) {
    if (i < 0) i = -i - 1;
    if (i > 63) i = 127 - i;
    return i;
}
__device__ __forceinline__ float ex2f(float x) {
    float r;
    asm("ex2.approx.ftz.f32 %0, %1;" : "=f"(r) : "f"(x));
    return r;
}
__device__ __forceinline__ void mma16816(float* c, const uint32_t* a, uint32_t b0, uint32_t b1) {
    asm volatile(
        "mma.sync.aligned.m16n8k16.row.col.f32.bf16.bf16.f32 "
        "{%0,%1,%2,%3}, {%4,%5,%6,%7}, {%8,%9}, {%0,%1,%2,%3};"
        : "+f"(c[0]), "+f"(c[1]), "+f"(c[2]), "+f"(c[3])
        : "r"(a[0]), "r"(a[1]), "r"(a[2]), "r"(a[3]), "r"(b0), "r"(b1));
}
__device__ __forceinline__ __nv_bfloat16 bf_hi(float v) { return __float2bfloat16(v); }
__device__ __forceinline__ __nv_bfloat16 bf_lo(float v) {
    __nv_bfloat16 h = __float2bfloat16(v);
    return __float2bfloat16(v - __bfloat162float(h));
}

// ---------------- prep: A fragments (symmetric-padded x, [hi|hi|lo] split) ----------------
__global__ void prep_a3f_kernel(const float* __restrict__ x) {
    int tid = blockIdx.x * blockDim.x + threadIdx.x;
    if (tid >= NR16 * NK16 * 32) return;
    int lane = tid & 31;
    int f = tid >> 5;
    int K16 = f % NK16;
    int R16 = f / NK16;
    int seg = (K16 * 16) >> 8;
    int kc  = ((K16 * 16) & 255) + (lane & 3) * 2;
    bool lo = (seg == 2);                    // A3 = [hi | hi | lo]

    int re = R16 * 16 + (lane >> 2);
    int ro = re + 8;

    const float* pe = nullptr;
    const float* po = nullptr;
    if (re < ROWS_REAL) {
        int b = re / 4900, rem = re - b * 4900;
        int hp = rem / 70, wp = rem - hp * 70;
        pe = x + ((((b << 6) + reflect64(hp - 3)) << 6) + reflect64(wp - 3)) * 256;
    }
    if (ro < ROWS_REAL) {
        int b = ro / 4900, rem = ro - b * 4900;
        int hp = rem / 70, wp = rem - hp * 70;
        po = x + ((((b << 6) + reflect64(hp - 3)) << 6) + reflect64(wp - 3)) * 256;
    }

    __nv_bfloat16 o[8];
#pragma unroll
    for (int h = 0; h < 2; h++) {
        float ve0 = pe ? pe[kc + h]     : 0.f;
        float vo0 = po ? po[kc + h]     : 0.f;
        float ve8 = pe ? pe[kc + 8 + h] : 0.f;
        float vo8 = po ? po[kc + 8 + h] : 0.f;
        o[0 + h] = lo ? bf_lo(ve0) : bf_hi(ve0);
        o[2 + h] = lo ? bf_lo(vo0) : bf_hi(vo0);
        o[4 + h] = lo ? bf_lo(ve8) : bf_hi(ve8);
        o[6 + h] = lo ? bf_lo(vo8) : bf_hi(vo8);
    }
    *(uint4*)(g_A3f + (size_t)tid * 8) = *(uint4*)o;
}

// ---------------- prep: B fragments (wcat^T, [hi|lo|hi] split) ----------------
__global__ void prep_b3f_kernel(const float* __restrict__ wq,
                                const float* __restrict__ wk,
                                const float* __restrict__ wv) {
    int tid = blockIdx.x * blockDim.x + threadIdx.x;
    if (tid >= NN8 * NK16 * 32) return;
    int lane = tid & 31;
    int f = tid >> 5;
    int K16 = f % NK16;
    int N8  = f / NK16;
    int seg = (K16 * 16) >> 8;
    int kc  = ((K16 * 16) & 255) + (lane & 3) * 2;
    bool lo = (seg == 1);                    // B3 = [hi | lo | hi]

    int n = N8 * 8 + (lane >> 2);
    int sel = n >> 8, cc = n & 255;
    const float* w = (sel == 0) ? wq : (sel == 1 ? wk : wv);

    __nv_bfloat16 o[4];
#pragma unroll
    for (int h = 0; h < 2; h++) {
        float v0 = w[(kc + h) * 256 + cc];
        float v8 = w[(kc + 8 + h) * 256 + cc];
        o[0 + h] = lo ? bf_lo(v0) : bf_hi(v0);
        o[2 + h] = lo ? bf_lo(v8) : bf_hi(v8);
    }
    *(uint2*)(g_B3f + (size_t)tid * 4) = *(uint2*)o;
}

// ---------------- prep: transposed bias window table Bwin[j][c] ----------------
__global__ void prep_bwin_kernel(const float* __restrict__ rh,
                                 const float* __restrict__ rw) {
    int idx = blockIdx.x * blockDim.x + threadIdx.x;
    if (idx >= 49 * 256) return;
    int j = idx >> 8;
    int c = idx & 255;
    int u = c * 49 + j;
    int ch = u & 255;
    int tap = u >> 8;
    int kh = (tap * 37) >> 8;
    int kw = tap - kh * 7;
    g_bwin[idx] = (ch < 128) ? rh[kh * 128 + ch] : rw[kw * 128 + (ch - 128)];
}

// ---------------- smem-free mma.sync GEMM: C[9856,768] = A3 . B3^T ----------------
// BM=64 BN=128, 8 warps (2x4), warp tile 32x32, 3 CTAs/SM for latency hiding.
__global__ __launch_bounds__(256, 3) void mma_gemm_kernel() {
    int tid = threadIdx.x;
    int lane = tid & 31, wid = tid >> 5;
    int wm = wid >> 2, wn = wid & 3;
    int fragR0 = blockIdx.y * 4  + wm * 2;    // R16 frag base (BM=64 -> 4 frags)
    int fragN0 = blockIdx.x * 16 + wn * 4;    // N8 frag base

    const uint4* Af = (const uint4*)g_A3f;
    const uint2* Bf = (const uint2*)g_B3f;

    const uint4* pA[2];
    const uint2* pB[4];
#pragma unroll
    for (int mt = 0; mt < 2; mt++) pA[mt] = Af + ((size_t)(fragR0 + mt) * NK16) * 32 + lane;
#pragma unroll
    for (int nt = 0; nt < 4; nt++) pB[nt] = Bf + ((size_t)(fragN0 + nt) * NK16) * 32 + lane;

    float acc[2][4][4];
#pragma unroll
    for (int i = 0; i < 2; i++)
#pragma unroll
        for (int j = 0; j < 4; j++)
#pragma unroll
            for (int v = 0; v < 4; v++) acc[i][j][v] = 0.f;

    uint4 a[2]; uint2 b[4];
    uint4 an[2]; uint2 bn[4];
#pragma unroll
    for (int mt = 0; mt < 2; mt++) a[mt] = pA[mt][0];
#pragma unroll
    for (int nt = 0; nt < 4; nt++) b[nt] = pB[nt][0];

#pragma unroll 4
    for (int kt = 0; kt < NK16; kt += 2) {
#pragma unroll
        for (int mt = 0; mt < 2; mt++) an[mt] = pA[mt][(kt + 1) * 32];
#pragma unroll
        for (int nt = 0; nt < 4; nt++) bn[nt] = pB[nt][(kt + 1) * 32];
#pragma unroll
        for (int mt = 0; mt < 2; mt++)
#pragma unroll
            for (int nt = 0; nt < 4; nt++)
                mma16816(acc[mt][nt], (const uint32_t*)&a[mt], b[nt].x, b[nt].y);
        if (kt + 2 < NK16) {
#pragma unroll
            for (int mt = 0; mt < 2; mt++) a[mt] = pA[mt][(kt + 2) * 32];
#pragma unroll
            for (int nt = 0; nt < 4; nt++) b[nt] = pB[nt][(kt + 2) * 32];
        }
#pragma unroll
        for (int mt = 0; mt < 2; mt++)
#pragma unroll
            for (int nt = 0; nt < 4; nt++)
                mma16816(acc[mt][nt], (const uint32_t*)&an[mt], bn[nt].x, bn[nt].y);
    }

    // epilogue: m16n8 fragments -> g_C
    int row0 = blockIdx.y * 64, col0 = blockIdx.x * 128;
    int qr = lane >> 2;
    int qc = (lane & 3) * 2;
#pragma unroll
    for (int mt = 0; mt < 2; mt++) {
#pragma unroll
        for (int nt = 0; nt < 4; nt++) {
            int rr = row0 + wm * 32 + mt * 16 + qr;
            int cc = col0 + wn * 32 + nt * 8 + qc;
            *(float2*)(g_C + (size_t)rr * 768 + cc)       = make_float2(acc[mt][nt][0], acc[mt][nt][1]);
            *(float2*)(g_C + (size_t)(rr + 8) * 768 + cc) = make_float2(acc[mt][nt][2], acc[mt][nt][3]);
        }
    }
}

// ---------------- attention: 4x4 spatial tile, branchless 2-base windows ----------------
// 10x10 window rows shared by 16 positions: 100 rows x [K 256f | V 256f] = 200 KB smem.
__global__ __launch_bounds__(512, 1) void attn_kernel(float* __restrict__ out) {
    extern __shared__ float sm[];          // 100 * 512 floats

    int t = threadIdx.x;
    int bid = blockIdx.x;
    int w4 = bid & 15, h4 = (bid >> 4) & 15, b = bid >> 8;
    int h0 = h4 * 4, w0 = w4 * 4;

    const float4* C4 = (const float4*)g_C;
    float4* sm4 = (float4*)sm;

    // stage K+V: 100 rows x 128 float4s = 12800 float4s, 25 per thread
#pragma unroll
    for (int i = 0; i < 25; i++) {
        int idx = i * 512 + t;
        int r = idx >> 7;                  // window row 0..99
        int which = (idx >> 6) & 1;        // 0=K, 1=V
        int ch4 = idx & 63;
        int rr10 = (r * 205) >> 11;        // r / 10 (exact for r < 103)
        int rc = r - rr10 * 10;
        int grow = (b * 70 + h0 + rr10) * 70 + (w0 + rc);
        sm4[r * 128 + (which << 6) + ch4] = C4[grow * 192 + 64 + (which << 6) + ch4];
    }
    __syncthreads();

    int slot = t >> 8;
    int c = t & 255;
    int u0 = c * 49;
    int tap0 = u0 >> 8;
    int ch0 = u0 & 255;
    int kh0 = (tap0 * 37) >> 8;
    int kw0 = tap0 - kh0 * 7;
    int n1 = 256 - ch0; if (n1 > 49) n1 = 49;
    int kh1 = kh0, kw1 = kw0 + 1;
    if (kw1 == 7) { kw1 = 0; kh1++; }

    float breg[49];
#pragma unroll
    for (int j = 0; j < 49; j++)
        breg[j] = __ldg(&g_bwin[j * 256 + c]);

#pragma unroll 1
    for (int p = 0; p < 8; p++) {
        int posid = slot * 8 + p;
        int dh = posid >> 2, dw = posid & 3;
        float q = g_C[((b * 70 + h0 + dh + 3) * 70 + (w0 + dw + 3)) * 768 + c];
        float ql2 = q * 1.4426950408889634f;

        int baseA = ((dh + kh0) * 10 + dw + kw0) * 512 + ch0;
        int baseB = ((dh + kh1) * 10 + dw + kw1) * 512 - n1;

        float s0 = 0.f, s1 = 0.f, a0 = 0.f, a1 = 0.f;
#pragma unroll
        for (int j = 0; j < 49; j++) {
            int a = (j < n1) ? baseA : baseB;
            float kv = sm[a + j];
            float vv = sm[a + j + 256];
            float e = ex2f(ql2 * kv);
            if (j & 1) { s1 += e; a1 += e * (vv + breg[j]); }
            else       { s0 += e; a0 += e * (vv + breg[j]); }
        }
        out[((b * 64 + h0 + dh) * 64 + (w0 + dw)) * 256 + c] = (a0 + a1) / (s0 + s1);
    }
}

// ---------------- launch ----------------
extern "C" void kernel_launch(void* const* d_in, const int* in_sizes, int n_in,
                              void* d_out, int out_size) {
    const float* x  = (const float*)d_in[0];
    const float* wq = (const float*)d_in[1];
    const float* wk = (const float*)d_in[2];
    const float* wv = (const float*)d_in[3];
    const float* rh = (const float*)d_in[4];
    const float* rw = (const float*)d_in[5];
    float* out = (float*)d_out;

    prep_a3f_kernel<<<(NR16 * NK16 * 32 + 255) / 256, 256>>>(x);
    prep_b3f_kernel<<<(NN8 * NK16 * 32 + 255) / 256, 256>>>(wq, wk, wv);
    prep_bwin_kernel<<<49, 256>>>(rh, rw);

    dim3 ggrid(6, 154);   // N-tiles x M-tiles (BM=64)
    mma_gemm_kernel<<<ggrid, 256>>>();

    cudaFuncSetAttribute(attn_kernel,
                         cudaFuncAttributeMaxDynamicSharedMemorySize, 204800);
    attn_kernel<<<512, 512, 204800>>>(out);
}

// round 10
// speedup vs baseline: 1.4522x; 1.1081x over previous
#include <cuda_runtime.h>
#include <cuda_bf16.h>
#include <cstdint>

#define ROWS_REAL 9800          // 2 * 70 * 70 padded-grid rows
#define ROWS_PAD  9856          // 616 * 16
#define NOUT      768           // q | kf | vf packed
#define K3        768           // split-K: [hi | hi | lo] x [hi | lo | hi]
#define NR16      616           // ROWS_PAD / 16
#define NK16      48            // K3 / 16
#define NN8       96            // NOUT / 8

// Fragment-linear operand storage:
//   A3f: [R16 frag][K16 frag][lane 0..31][8 bf16]   (a0|a1|a2|a3 pairs)
//   B3f: [N8 frag][K16 frag][lane 0..31][4 bf16]    (b0|b1 pairs)
__device__ __nv_bfloat16 g_A3f[NR16 * NK16 * 32 * 8];
__device__ __nv_bfloat16 g_B3f[NN8 * NK16 * 32 * 4];
__device__ float g_C[ROWS_PAD * NOUT];          // [q | kf | vf]
__device__ float g_bwin[49 * 256];              // transposed bias window [j][c]

// ---------------- helpers ----------------
__device__ __forceinline__ int reflect64(int i) {
    if (i < 0) i = -i - 1;
    if (i > 63) i = 127 - i;
    return i;
}
__device__ __forceinline__ float ex2f(float x) {
    float r;
    asm("ex2.approx.ftz.f32 %0, %1;" : "=f"(r) : "f"(x));
    return r;
}
__device__ __forceinline__ void mma16816(float* c, const uint32_t* a, uint32_t b0, uint32_t b1) {
    asm volatile(
        "mma.sync.aligned.m16n8k16.row.col.f32.bf16.bf16.f32 "
        "{%0,%1,%2,%3}, {%4,%5,%6,%7}, {%8,%9}, {%0,%1,%2,%3};"
        : "+f"(c[0]), "+f"(c[1]), "+f"(c[2]), "+f"(c[3])
        : "r"(a[0]), "r"(a[1]), "r"(a[2]), "r"(a[3]), "r"(b0), "r"(b1));
}
__device__ __forceinline__ __nv_bfloat16 bf_hi(float v) { return __float2bfloat16(v); }
__device__ __forceinline__ __nv_bfloat16 bf_lo(float v) {
    __nv_bfloat16 h = __float2bfloat16(v);
    return __float2bfloat16(v - __bfloat162float(h));
}

// ---------------- prep: A fragments (symmetric-padded x, [hi|hi|lo] split) ----------------
__global__ void prep_a3f_kernel(const float* __restrict__ x) {
    int tid = blockIdx.x * blockDim.x + threadIdx.x;
    if (tid >= NR16 * NK16 * 32) return;
    int lane = tid & 31;
    int f = tid >> 5;
    int K16 = f % NK16;
    int R16 = f / NK16;
    int seg = (K16 * 16) >> 8;
    int kc  = ((K16 * 16) & 255) + (lane & 3) * 2;
    bool lo = (seg == 2);                    // A3 = [hi | hi | lo]

    int re = R16 * 16 + (lane >> 2);
    int ro = re + 8;

    const float* pe = nullptr;
    const float* po = nullptr;
    if (re < ROWS_REAL) {
        int b = re / 4900, rem = re - b * 4900;
        int hp = rem / 70, wp = rem - hp * 70;
        pe = x + ((((b << 6) + reflect64(hp - 3)) << 6) + reflect64(wp - 3)) * 256;
    }
    if (ro < ROWS_REAL) {
        int b = ro / 4900, rem = ro - b * 4900;
        int hp = rem / 70, wp = rem - hp * 70;
        po = x + ((((b << 6) + reflect64(hp - 3)) << 6) + reflect64(wp - 3)) * 256;
    }

    __nv_bfloat16 o[8];
#pragma unroll
    for (int h = 0; h < 2; h++) {
        float ve0 = pe ? pe[kc + h]     : 0.f;
        float vo0 = po ? po[kc + h]     : 0.f;
        float ve8 = pe ? pe[kc + 8 + h] : 0.f;
        float vo8 = po ? po[kc + 8 + h] : 0.f;
        o[0 + h] = lo ? bf_lo(ve0) : bf_hi(ve0);
        o[2 + h] = lo ? bf_lo(vo0) : bf_hi(vo0);
        o[4 + h] = lo ? bf_lo(ve8) : bf_hi(ve8);
        o[6 + h] = lo ? bf_lo(vo8) : bf_hi(vo8);
    }
    *(uint4*)(g_A3f + (size_t)tid * 8) = *(uint4*)o;
}

// ---------------- prep: B fragments (wcat^T, [hi|lo|hi] split) ----------------
__global__ void prep_b3f_kernel(const float* __restrict__ wq,
                                const float* __restrict__ wk,
                                const float* __restrict__ wv) {
    int tid = blockIdx.x * blockDim.x + threadIdx.x;
    if (tid >= NN8 * NK16 * 32) return;
    int lane = tid & 31;
    int f = tid >> 5;
    int K16 = f % NK16;
    int N8  = f / NK16;
    int seg = (K16 * 16) >> 8;
    int kc  = ((K16 * 16) & 255) + (lane & 3) * 2;
    bool lo = (seg == 1);                    // B3 = [hi | lo | hi]

    int n = N8 * 8 + (lane >> 2);
    int sel = n >> 8, cc = n & 255;
    const float* w = (sel == 0) ? wq : (sel == 1 ? wk : wv);

    __nv_bfloat16 o[4];
#pragma unroll
    for (int h = 0; h < 2; h++) {
        float v0 = w[(kc + h) * 256 + cc];
        float v8 = w[(kc + 8 + h) * 256 + cc];
        o[0 + h] = lo ? bf_lo(v0) : bf_hi(v0);
        o[2 + h] = lo ? bf_lo(v8) : bf_hi(v8);
    }
    *(uint2*)(g_B3f + (size_t)tid * 4) = *(uint2*)o;
}

// ---------------- prep: transposed bias window table Bwin[j][c] ----------------
__global__ void prep_bwin_kernel(const float* __restrict__ rh,
                                 const float* __restrict__ rw) {
    int idx = blockIdx.x * blockDim.x + threadIdx.x;
    if (idx >= 49 * 256) return;
    int j = idx >> 8;
    int c = idx & 255;
    int u = c * 49 + j;
    int ch = u & 255;
    int tap = u >> 8;
    int kh = (tap * 37) >> 8;
    int kw = tap - kh * 7;
    g_bwin[idx] = (ch < 128) ? rh[kh * 128 + ch] : rw[kw * 128 + (ch - 128)];
}

// ---------------- smem-free mma.sync GEMM (R8 config): C = A3 . B3^T ----------------
// BM=128 BN=128, 8 warps (2x4), warp tile 64x32: 4 LDG.128 + 4 LDG.64 + 16 MMA / K16.
__global__ __launch_bounds__(256, 2) void mma_gemm_kernel() {
    int tid = threadIdx.x;
    int lane = tid & 31, wid = tid >> 5;
    int wm = wid >> 2, wn = wid & 3;
    int fragR0 = blockIdx.y * 8  + wm * 4;    // R16 frag base
    int fragN0 = blockIdx.x * 16 + wn * 4;    // N8 frag base

    const uint4* Af = (const uint4*)g_A3f;
    const uint2* Bf = (const uint2*)g_B3f;

    const uint4* pA[4];
    const uint2* pB[4];
#pragma unroll
    for (int mt = 0; mt < 4; mt++) pA[mt] = Af + ((size_t)(fragR0 + mt) * NK16) * 32 + lane;
#pragma unroll
    for (int nt = 0; nt < 4; nt++) pB[nt] = Bf + ((size_t)(fragN0 + nt) * NK16) * 32 + lane;

    float acc[4][4][4];
#pragma unroll
    for (int i = 0; i < 4; i++)
#pragma unroll
        for (int j = 0; j < 4; j++)
#pragma unroll
            for (int v = 0; v < 4; v++) acc[i][j][v] = 0.f;

    uint4 a[4]; uint2 b[4];
    uint4 an[4]; uint2 bn[4];
#pragma unroll
    for (int mt = 0; mt < 4; mt++) a[mt] = pA[mt][0];
#pragma unroll
    for (int nt = 0; nt < 4; nt++) b[nt] = pB[nt][0];

#pragma unroll 4
    for (int kt = 0; kt < NK16; kt += 2) {
#pragma unroll
        for (int mt = 0; mt < 4; mt++) an[mt] = pA[mt][(kt + 1) * 32];
#pragma unroll
        for (int nt = 0; nt < 4; nt++) bn[nt] = pB[nt][(kt + 1) * 32];
#pragma unroll
        for (int mt = 0; mt < 4; mt++)
#pragma unroll
            for (int nt = 0; nt < 4; nt++)
                mma16816(acc[mt][nt], (const uint32_t*)&a[mt], b[nt].x, b[nt].y);
        if (kt + 2 < NK16) {
#pragma unroll
            for (int mt = 0; mt < 4; mt++) a[mt] = pA[mt][(kt + 2) * 32];
#pragma unroll
            for (int nt = 0; nt < 4; nt++) b[nt] = pB[nt][(kt + 2) * 32];
        }
#pragma unroll
        for (int mt = 0; mt < 4; mt++)
#pragma unroll
            for (int nt = 0; nt < 4; nt++)
                mma16816(acc[mt][nt], (const uint32_t*)&an[mt], bn[nt].x, bn[nt].y);
    }

    // epilogue: m16n8 fragments -> g_C
    int row0 = blockIdx.y * 128, col0 = blockIdx.x * 128;
    int qr = lane >> 2;
    int qc = (lane & 3) * 2;
#pragma unroll
    for (int mt = 0; mt < 4; mt++) {
#pragma unroll
        for (int nt = 0; nt < 4; nt++) {
            int rr = row0 + wm * 64 + mt * 16 + qr;
            int cc = col0 + wn * 32 + nt * 8 + qc;
            *(float2*)(g_C + (size_t)rr * 768 + cc)       = make_float2(acc[mt][nt][0], acc[mt][nt][1]);
            *(float2*)(g_C + (size_t)(rr + 8) * 768 + cc) = make_float2(acc[mt][nt][2], acc[mt][nt][3]);
        }
    }
}

// ---------------- attention: 4x4 spatial tile (R9 config) ----------------
// 10x10 window rows shared by 16 positions: 100 rows x [K 256f | V 256f] = 200 KB smem.
__global__ __launch_bounds__(512, 1) void attn_kernel(float* __restrict__ out) {
    extern __shared__ float sm[];          // 100 * 512 floats

    int t = threadIdx.x;
    int bid = blockIdx.x;
    int w4 = bid & 15, h4 = (bid >> 4) & 15, b = bid >> 8;
    int h0 = h4 * 4, w0 = w4 * 4;

    const float4* C4 = (const float4*)g_C;
    float4* sm4 = (float4*)sm;

    // stage K+V: 100 rows x 128 float4s = 12800 float4s, 25 per thread
#pragma unroll
    for (int i = 0; i < 25; i++) {
        int idx = i * 512 + t;
        int r = idx >> 7;                  // window row 0..99
        int which = (idx >> 6) & 1;        // 0=K, 1=V
        int ch4 = idx & 63;
        int rr10 = (r * 205) >> 11;        // r / 10 (exact for r < 103)
        int rc = r - rr10 * 10;
        int grow = (b * 70 + h0 + rr10) * 70 + (w0 + rc);
        sm4[r * 128 + (which << 6) + ch4] = C4[grow * 192 + 64 + (which << 6) + ch4];
    }
    __syncthreads();

    int slot = t >> 8;
    int c = t & 255;
    int u0 = c * 49;
    int tap0 = u0 >> 8;
    int ch0 = u0 & 255;
    int kh0 = (tap0 * 37) >> 8;
    int kw0 = tap0 - kh0 * 7;
    int n1 = 256 - ch0; if (n1 > 49) n1 = 49;
    int kh1 = kh0, kw1 = kw0 + 1;
    if (kw1 == 7) { kw1 = 0; kh1++; }

    float breg[49];
#pragma unroll
    for (int j = 0; j < 49; j++)
        breg[j] = __ldg(&g_bwin[j * 256 + c]);

#pragma unroll 1
    for (int p = 0; p < 8; p++) {
        int posid = slot * 8 + p;
        int dh = posid >> 2, dw = posid & 3;
        float q = g_C[((b * 70 + h0 + dh + 3) * 70 + (w0 + dw + 3)) * 768 + c];
        float ql2 = q * 1.4426950408889634f;

        int baseA = ((dh + kh0) * 10 + dw + kw0) * 512 + ch0;
        int baseB = ((dh + kh1) * 10 + dw + kw1) * 512 - n1;

        float s0 = 0.f, s1 = 0.f, a0 = 0.f, a1 = 0.f;
#pragma unroll
        for (int j = 0; j < 49; j++) {
            int a = (j < n1) ? baseA : baseB;
            float kv = sm[a + j];
            float vv = sm[a + j + 256];
            float e = ex2f(ql2 * kv);
            if (j & 1) { s1 += e; a1 += e * (vv + breg[j]); }
            else       { s0 += e; a0 += e * (vv + breg[j]); }
        }
        out[((b * 64 + h0 + dh) * 64 + (w0 + dw)) * 256 + c] = (a0 + a1) / (s0 + s1);
    }
}

// ---------------- launch ----------------
extern "C" void kernel_launch(void* const* d_in, const int* in_sizes, int n_in,
                              void* d_out, int out_size) {
    const float* x  = (const float*)d_in[0];
    const float* wq = (const float*)d_in[1];
    const float* wk = (const float*)d_in[2];
    const float* wv = (const float*)d_in[3];
    const float* rh = (const float*)d_in[4];
    const float* rw = (const float*)d_in[5];
    float* out = (float*)d_out;

    prep_a3f_kernel<<<(NR16 * NK16 * 32 + 255) / 256, 256>>>(x);
    prep_b3f_kernel<<<(NN8 * NK16 * 32 + 255) / 256, 256>>>(wq, wk, wv);
    prep_bwin_kernel<<<49, 256>>>(rh, rw);

    dim3 ggrid(6, 77);   // N-tiles x M-tiles (BM=128)
    mma_gemm_kernel<<<ggrid, 256>>>();

    cudaFuncSetAttribute(attn_kernel,
                         cudaFuncAttributeMaxDynamicSharedMemorySize, 204800);
    attn_kernel<<<512, 512, 204800>>>(out);
}

// round 11
// speedup vs baseline: 1.6314x; 1.1234x over previous
#include <cuda_runtime.h>
#include <cuda_fp16.h>
#include <cstdint>

#define ROWS_REAL 9800          // 2 * 70 * 70 padded-grid rows
#define ROWS_PAD  9856          // 616 * 16
#define NOUT      768           // q | kf | vf packed
#define NR16      616           // ROWS_PAD / 16
#define NK16A     32            // A K16 steps: [hi(256) | lo(256)]
#define NK16B     16            // B K16 steps: hi only (reused for both halves)
#define NN8       96            // NOUT / 8

// Fragment-linear operand storage (fp16 split-2):
//   A2f: [R16 frag][K16 0..31][lane][8 halfs]  (a0|a1|a2|a3 pairs); K16>=16 = lo seg
//   B2f: [N8 frag][K16 0..15][lane][4 halfs]   (b0|b1 pairs); hi only
__device__ __half g_A2f[NR16 * NK16A * 32 * 8];
__device__ __half g_B2f[NN8 * NK16B * 32 * 4];
__device__ float g_C[ROWS_PAD * NOUT];          // [q | kf | vf]
__device__ float g_bwin[49 * 256];              // transposed bias window [j][c]

// ---------------- helpers ----------------
__device__ __forceinline__ int reflect64(int i) {
    if (i < 0) i = -i - 1;
    if (i > 63) i = 127 - i;
    return i;
}
__device__ __forceinline__ float ex2f(float x) {
    float r;
    asm("ex2.approx.ftz.f32 %0, %1;" : "=f"(r) : "f"(x));
    return r;
}
__device__ __forceinline__ void mma16816(float* c, const uint32_t* a, uint32_t b0, uint32_t b1) {
    asm volatile(
        "mma.sync.aligned.m16n8k16.row.col.f32.f16.f16.f32 "
        "{%0,%1,%2,%3}, {%4,%5,%6,%7}, {%8,%9}, {%0,%1,%2,%3};"
        : "+f"(c[0]), "+f"(c[1]), "+f"(c[2]), "+f"(c[3])
        : "r"(a[0]), "r"(a[1]), "r"(a[2]), "r"(a[3]), "r"(b0), "r"(b1));
}
__device__ __forceinline__ __half hf_hi(float v) { return __float2half_rn(v); }
__device__ __forceinline__ __half hf_lo(float v) {
    __half h = __float2half_rn(v);
    return __float2half_rn(v - __half2float(h));
}

// ---------------- prep: A fragments (symmetric-padded x, fp16 [hi|lo]) ----------------
__global__ void prep_a2f_kernel(const float* __restrict__ x) {
    int tid = blockIdx.x * blockDim.x + threadIdx.x;
    if (tid >= NR16 * NK16A * 32) return;
    int lane = tid & 31;
    int f = tid >> 5;
    int K16 = f % NK16A;
    int R16 = f / NK16A;
    bool lo = (K16 >= 16);
    int kc  = (K16 & 15) * 16 + (lane & 3) * 2;

    int re = R16 * 16 + (lane >> 2);
    int ro = re + 8;

    const float* pe = nullptr;
    const float* po = nullptr;
    if (re < ROWS_REAL) {
        int b = re / 4900, rem = re - b * 4900;
        int hp = rem / 70, wp = rem - hp * 70;
        pe = x + ((((b << 6) + reflect64(hp - 3)) << 6) + reflect64(wp - 3)) * 256;
    }
    if (ro < ROWS_REAL) {
        int b = ro / 4900, rem = ro - b * 4900;
        int hp = rem / 70, wp = rem - hp * 70;
        po = x + ((((b << 6) + reflect64(hp - 3)) << 6) + reflect64(wp - 3)) * 256;
    }

    __half o[8];
#pragma unroll
    for (int h = 0; h < 2; h++) {
        float ve0 = pe ? pe[kc + h]     : 0.f;
        float vo0 = po ? po[kc + h]     : 0.f;
        float ve8 = pe ? pe[kc + 8 + h] : 0.f;
        float vo8 = po ? po[kc + 8 + h] : 0.f;
        o[0 + h] = lo ? hf_lo(ve0) : hf_hi(ve0);   // a0
        o[2 + h] = lo ? hf_lo(vo0) : hf_hi(vo0);   // a1
        o[4 + h] = lo ? hf_lo(ve8) : hf_hi(ve8);   // a2
        o[6 + h] = lo ? hf_lo(vo8) : hf_hi(vo8);   // a3
    }
    *(uint4*)(g_A2f + (size_t)tid * 8) = *(uint4*)o;
}

// ---------------- prep: B fragments (wcat^T, fp16 hi only) ----------------
__global__ void prep_b2f_kernel(const float* __restrict__ wq,
                                const float* __restrict__ wk,
                                const float* __restrict__ wv) {
    int tid = blockIdx.x * blockDim.x + threadIdx.x;
    if (tid >= NN8 * NK16B * 32) return;
    int lane = tid & 31;
    int f = tid >> 5;
    int K16 = f % NK16B;
    int N8  = f / NK16B;
    int kc  = K16 * 16 + (lane & 3) * 2;

    int n = N8 * 8 + (lane >> 2);
    int sel = n >> 8, cc = n & 255;
    const float* w = (sel == 0) ? wq : (sel == 1 ? wk : wv);

    __half o[4];
#pragma unroll
    for (int h = 0; h < 2; h++) {
        o[0 + h] = hf_hi(w[(kc + h) * 256 + cc]);      // b0
        o[2 + h] = hf_hi(w[(kc + 8 + h) * 256 + cc]);  // b1
    }
    *(uint2*)(g_B2f + (size_t)tid * 4) = *(uint2*)o;
}

// ---------------- prep: transposed bias window table Bwin[j][c] ----------------
__global__ void prep_bwin_kernel(const float* __restrict__ rh,
                                 const float* __restrict__ rw) {
    int idx = blockIdx.x * blockDim.x + threadIdx.x;
    if (idx >= 49 * 256) return;
    int j = idx >> 8;
    int c = idx & 255;
    int u = c * 49 + j;
    int ch = u & 255;
    int tap = u >> 8;
    int kh = (tap * 37) >> 8;
    int kw = tap - kh * 7;
    g_bwin[idx] = (ch < 128) ? rh[kh * 128 + ch] : rw[kw * 128 + (ch - 128)];
}

// ---------------- smem-free mma.sync GEMM (fp16 split-2): C = A2 . B2^T ----------------
// BM=128 BN=128, 8 warps (2x4), warp tile 64x32. 32 K16 steps; B reused via kt&15.
__global__ __launch_bounds__(256, 2) void mma_gemm_kernel() {
    int tid = threadIdx.x;
    int lane = tid & 31, wid = tid >> 5;
    int wm = wid >> 2, wn = wid & 3;
    int fragR0 = blockIdx.y * 8  + wm * 4;    // R16 frag base
    int fragN0 = blockIdx.x * 16 + wn * 4;    // N8 frag base

    const uint4* Af = (const uint4*)g_A2f;
    const uint2* Bf = (const uint2*)g_B2f;

    const uint4* pA[4];
    const uint2* pB[4];
#pragma unroll
    for (int mt = 0; mt < 4; mt++) pA[mt] = Af + ((size_t)(fragR0 + mt) * NK16A) * 32 + lane;
#pragma unroll
    for (int nt = 0; nt < 4; nt++) pB[nt] = Bf + ((size_t)(fragN0 + nt) * NK16B) * 32 + lane;

    float acc[4][4][4];
#pragma unroll
    for (int i = 0; i < 4; i++)
#pragma unroll
        for (int j = 0; j < 4; j++)
#pragma unroll
            for (int v = 0; v < 4; v++) acc[i][j][v] = 0.f;

    uint4 a[4]; uint2 b[4];
    uint4 an[4]; uint2 bn[4];
#pragma unroll
    for (int mt = 0; mt < 4; mt++) a[mt] = pA[mt][0];
#pragma unroll
    for (int nt = 0; nt < 4; nt++) b[nt] = pB[nt][0];

#pragma unroll 4
    for (int kt = 0; kt < NK16A; kt += 2) {
#pragma unroll
        for (int mt = 0; mt < 4; mt++) an[mt] = pA[mt][(kt + 1) * 32];
#pragma unroll
        for (int nt = 0; nt < 4; nt++) bn[nt] = pB[nt][((kt + 1) & 15) * 32];
#pragma unroll
        for (int mt = 0; mt < 4; mt++)
#pragma unroll
            for (int nt = 0; nt < 4; nt++)
                mma16816(acc[mt][nt], (const uint32_t*)&a[mt], b[nt].x, b[nt].y);
        if (kt + 2 < NK16A) {
#pragma unroll
            for (int mt = 0; mt < 4; mt++) a[mt] = pA[mt][(kt + 2) * 32];
#pragma unroll
            for (int nt = 0; nt < 4; nt++) b[nt] = pB[nt][((kt + 2) & 15) * 32];
        }
#pragma unroll
        for (int mt = 0; mt < 4; mt++)
#pragma unroll
            for (int nt = 0; nt < 4; nt++)
                mma16816(acc[mt][nt], (const uint32_t*)&an[mt], bn[nt].x, bn[nt].y);
    }

    // epilogue: m16n8 fragments -> g_C
    int row0 = blockIdx.y * 128, col0 = blockIdx.x * 128;
    int qr = lane >> 2;
    int qc = (lane & 3) * 2;
#pragma unroll
    for (int mt = 0; mt < 4; mt++) {
#pragma unroll
        for (int nt = 0; nt < 4; nt++) {
            int rr = row0 + wm * 64 + mt * 16 + qr;
            int cc = col0 + wn * 32 + nt * 8 + qc;
            *(float2*)(g_C + (size_t)rr * 768 + cc)       = make_float2(acc[mt][nt][0], acc[mt][nt][1]);
            *(float2*)(g_C + (size_t)(rr + 8) * 768 + cc) = make_float2(acc[mt][nt][2], acc[mt][nt][3]);
        }
    }
}

// ---------------- attention: 4x4 spatial tile (proven R9/R10 config) ----------------
// 10x10 window rows shared by 16 positions: 100 rows x [K 256f | V 256f] = 200 KB smem.
__global__ __launch_bounds__(512, 1) void attn_kernel(float* __restrict__ out) {
    extern __shared__ float sm[];          // 100 * 512 floats

    int t = threadIdx.x;
    int bid = blockIdx.x;
    int w4 = bid & 15, h4 = (bid >> 4) & 15, b = bid >> 8;
    int h0 = h4 * 4, w0 = w4 * 4;

    const float4* C4 = (const float4*)g_C;
    float4* sm4 = (float4*)sm;

    // stage K+V: 100 rows x 128 float4s = 12800 float4s, 25 per thread
#pragma unroll
    for (int i = 0; i < 25; i++) {
        int idx = i * 512 + t;
        int r = idx >> 7;                  // window row 0..99
        int which = (idx >> 6) & 1;        // 0=K, 1=V
        int ch4 = idx & 63;
        int rr10 = (r * 205) >> 11;        // r / 10 (exact for r < 103)
        int rc = r - rr10 * 10;
        int grow = (b * 70 + h0 + rr10) * 70 + (w0 + rc);
        sm4[r * 128 + (which << 6) + ch4] = C4[grow * 192 + 64 + (which << 6) + ch4];
    }
    __syncthreads();

    int slot = t >> 8;
    int c = t & 255;
    int u0 = c * 49;
    int tap0 = u0 >> 8;
    int ch0 = u0 & 255;
    int kh0 = (tap0 * 37) >> 8;
    int kw0 = tap0 - kh0 * 7;
    int n1 = 256 - ch0; if (n1 > 49) n1 = 49;
    int kh1 = kh0, kw1 = kw0 + 1;
    if (kw1 == 7) { kw1 = 0; kh1++; }

    float breg[49];
#pragma unroll
    for (int j = 0; j < 49; j++)
        breg[j] = __ldg(&g_bwin[j * 256 + c]);

#pragma unroll 1
    for (int p = 0; p < 8; p++) {
        int posid = slot * 8 + p;
        int dh = posid >> 2, dw = posid & 3;
        float q = g_C[((b * 70 + h0 + dh + 3) * 70 + (w0 + dw + 3)) * 768 + c];
        float ql2 = q * 1.4426950408889634f;

        int baseA = ((dh + kh0) * 10 + dw + kw0) * 512 + ch0;
        int baseB = ((dh + kh1) * 10 + dw + kw1) * 512 - n1;

        float s0 = 0.f, s1 = 0.f, a0 = 0.f, a1 = 0.f;
#pragma unroll
        for (int j = 0; j < 49; j++) {
            int a = (j < n1) ? baseA : baseB;
            float kv = sm[a + j];
            float vv = sm[a + j + 256];
            float e = ex2f(ql2 * kv);
            if (j & 1) { s1 += e; a1 += e * (vv + breg[j]); }
            else       { s0 += e; a0 += e * (vv + breg[j]); }
        }
        out[((b * 64 + h0 + dh) * 64 + (w0 + dw)) * 256 + c] = (a0 + a1) / (s0 + s1);
    }
}

// ---------------- launch ----------------
extern "C" void kernel_launch(void* const* d_in, const int* in_sizes, int n_in,
                              void* d_out, int out_size) {
    const float* x  = (const float*)d_in[0];
    const float* wq = (const float*)d_in[1];
    const float* wk = (const float*)d_in[2];
    const float* wv = (const float*)d_in[3];
    const float* rh = (const float*)d_in[4];
    const float* rw = (const float*)d_in[5];
    float* out = (float*)d_out;

    prep_a2f_kernel<<<(NR16 * NK16A * 32 + 255) / 256, 256>>>(x);
    prep_b2f_kernel<<<(NN8 * NK16B * 32 + 255) / 256, 256>>>(wq, wk, wv);
    prep_bwin_kernel<<<49, 256>>>(rh, rw);

    dim3 ggrid(6, 77);   // N-tiles x M-tiles (BM=128)
    mma_gemm_kernel<<<ggrid, 256>>>();

    cudaFuncSetAttribute(attn_kernel,
                         cudaFuncAttributeMaxDynamicSharedMemorySize, 204800);
    attn_kernel<<<512, 512, 204800>>>(out);
}